// round 1
// baseline (speedup 1.0000x reference)
#include <cuda_runtime.h>
#include <math.h>
#include <stdint.h>
#include <stddef.h>

// Problem constants
#define Bv   1024
#define Tv   256
#define EH   256
#define DH   512
#define ZL   128
#define PTc  5
#define OUTC 123
#define NBLK 148
#define NTHR 256

// ---------------- device scratch (static, no allocation) ----------------
__device__ float d_WhhF[4*EH*EH];     // encoder fwd recurrent, gate-interleaved [1024][256]
__device__ float d_WihF[4*EH*PTc];    // encoder fwd input, interleaved [1024][5]
__device__ float d_bF[4*EH];          // encoder fwd bias, interleaved
__device__ float d_WhhD[4*DH*DH];     // decoder recurrent, interleaved [2048][512]
__device__ float d_WihS[4*DH*PTc];    // decoder stroke-input, interleaved [2048][5]
__device__ float d_hE[2][Bv*EH];      // encoder h double buffer
__device__ float d_cE[Bv*EH];
__device__ float d_hback[Bv*EH];      // backward-dir h (single step)
__device__ float d_z[Bv*ZL];
__device__ float d_hD[2][Bv*DH];      // decoder h double buffer
__device__ float d_cD[Bv*DH];
__device__ float d_zproj[Bv*4*DH];    // z @ Wih_z^T + b  (interleaved) [1024][2048]
__device__ float d_qpart[Tv*16];      // deterministic per-(step, row-tile) exp_qk partial sums
__device__ unsigned g_count;
__device__ volatile unsigned g_gen;

// ---------------- helpers ----------------
__device__ __forceinline__ float sigf(float x) { return 1.f / (1.f + __expf(-x)); }
__device__ __forceinline__ float tanh_f(float x) {
    float ax = fabsf(x);
    float e = __expf(2.f * ax);
    float t = 1.f - 2.f / (e + 1.f);   // e=inf -> t=1
    return copysignf(t, x);
}
__device__ __forceinline__ float wsum32(float v) {
    #pragma unroll
    for (int o = 16; o; o >>= 1) v += __shfl_xor_sync(0xffffffffu, v, o);
    return v;
}
__device__ __forceinline__ float wmax32(float v) {
    #pragma unroll
    for (int o = 16; o; o >>= 1) v = fmaxf(v, __shfl_xor_sync(0xffffffffu, v, o));
    return v;
}

// software grid barrier (all NBLK blocks co-resident: 1 block/SM, 148 <= 152 SMs)
__device__ __forceinline__ void grid_sync() {
    __threadfence();
    __syncthreads();
    if (threadIdx.x == 0) {
        unsigned gen = g_gen;
        if (atomicAdd(&g_count, 1u) == NBLK - 1) {
            g_count = 0;
            __threadfence();
            g_gen = gen + 1;
        } else {
            while (g_gen == gen) { __nanosleep(128); }
        }
    }
    __syncthreads();
    __threadfence();
}

// ---------------- fused gate GEMM + LSTM cell update ----------------
// Tile: 64 rows x 128 cols (= 32 hidden units x 4 gates). 256 threads, 4x8 per thread.
// out[b][n] = init(b,n) + x(b,:) @ Wih5[n,:]^T + hprev(b,:) @ W[n,:]^T, then cell update.
__device__ __forceinline__ void gate_tile_impl(
    const float* __restrict__ hprev,   // [Bv][K]   (K == H)
    const float* __restrict__ W,       // [4H][K]   interleaved
    const float* __restrict__ Wih5,    // [4H][5]   interleaved
    const float* __restrict__ zproj,   // [Bv][4H]  or nullptr (then bias used)
    const float* __restrict__ bias,    // [4H]      interleaved
    const float* __restrict__ s, int xt,   // xt < 0 -> s0 = (0,0,1,0,0)
    float* __restrict__ cbuf, float* __restrict__ hnext,  // [Bv][H]
    int row0, int col0, int K, int H,
    float (*As)[68], float (*Bs)[132])
{
    const int tid = threadIdx.x;
    const int tx = tid & 15, ty = tid >> 4;
    const int N4 = 4 * H;

    int ncol[8];
    #pragma unroll
    for (int j = 0; j < 8; j++) ncol[j] = col0 + ((j >> 2) << 6) + tx * 4 + (j & 3);

    float xr[4][5];
    #pragma unroll
    for (int i = 0; i < 4; i++) {
        int row = row0 + ty * 4 + i;
        if (xt < 0) {
            xr[i][0] = 0.f; xr[i][1] = 0.f; xr[i][2] = 1.f; xr[i][3] = 0.f; xr[i][4] = 0.f;
        } else {
            const float* xp = s + ((size_t)row * Tv + xt) * PTc;
            #pragma unroll
            for (int k = 0; k < 5; k++) xr[i][k] = xp[k];
        }
    }

    float acc[4][8];
    if (zproj) {
        #pragma unroll
        for (int i = 0; i < 4; i++) {
            const float* zp = zproj + (size_t)(row0 + ty * 4 + i) * N4;
            #pragma unroll
            for (int j = 0; j < 8; j++) acc[i][j] = zp[ncol[j]];
        }
    } else {
        #pragma unroll
        for (int j = 0; j < 8; j++) {
            float bi = bias[ncol[j]];
            #pragma unroll
            for (int i = 0; i < 4; i++) acc[i][j] = bi;
        }
    }
    #pragma unroll
    for (int j = 0; j < 8; j++) {
        #pragma unroll
        for (int k = 0; k < 5; k++) {
            float w = Wih5[ncol[j] * 5 + k];
            #pragma unroll
            for (int i = 0; i < 4; i++) acc[i][j] += xr[i][k] * w;
        }
    }

    for (int kb = 0; kb < K; kb += 16) {
        #pragma unroll
        for (int l = 0; l < 4; l++) {
            int idx = tid + l * 256;
            int r = idx >> 4, kk = idx & 15;
            As[kk][r] = hprev[(size_t)(row0 + r) * K + kb + kk];
        }
        #pragma unroll
        for (int l = 0; l < 8; l++) {
            int idx = tid + l * 256;
            int n = idx >> 4, kk = idx & 15;
            Bs[kk][n] = W[(size_t)(col0 + n) * K + kb + kk];
        }
        __syncthreads();
        #pragma unroll
        for (int kk = 0; kk < 16; kk++) {
            float a[4], bv[8];
            #pragma unroll
            for (int i = 0; i < 4; i++) a[i] = As[kk][ty * 4 + i];
            #pragma unroll
            for (int j = 0; j < 8; j++) bv[j] = Bs[kk][((j >> 2) << 6) + tx * 4 + (j & 3)];
            #pragma unroll
            for (int i = 0; i < 4; i++)
                #pragma unroll
                for (int j = 0; j < 8; j++) acc[i][j] += a[i] * bv[j];
        }
        __syncthreads();
    }

    // fused LSTM cell update: each thread owns 2 complete units x 4 rows
    #pragma unroll
    for (int i = 0; i < 4; i++) {
        int row = row0 + ty * 4 + i;
        #pragma unroll
        for (int jj = 0; jj < 2; jj++) {
            int u = (col0 + jj * 64 + tx * 4) >> 2;
            float gi = acc[i][jj * 4 + 0];
            float gf = acc[i][jj * 4 + 1];
            float gg = acc[i][jj * 4 + 2];
            float go = acc[i][jj * 4 + 3];
            size_t p = (size_t)row * H + u;
            float c = sigf(gf) * cbuf[p] + sigf(gi) * tanh_f(gg);
            cbuf[p] = c;
            hnext[p] = sigf(go) * tanh_f(c);
        }
    }
}

// ---------------- y projection + mixture transforms for one 64-row tile ----------------
__device__ __forceinline__ void y_tile(
    const float* __restrict__ hcur, const float* __restrict__ Wout,
    const float* __restrict__ bout, float* __restrict__ out,
    int tstep, int row0,
    float (*As)[68], float (*Bs)[132], float (*ys)[124], float* wsum)
{
    const int tid = threadIdx.x;
    const int tx = tid & 15, ty = tid >> 4;

    float acc[4][8];
    #pragma unroll
    for (int j = 0; j < 8; j++) {
        int n = tx * 8 + j;
        float bi = (n < OUTC) ? bout[n] : 0.f;
        #pragma unroll
        for (int i = 0; i < 4; i++) acc[i][j] = bi;
    }

    for (int kb = 0; kb < DH; kb += 16) {
        #pragma unroll
        for (int l = 0; l < 4; l++) {
            int idx = tid + l * 256;
            int r = idx >> 4, kk = idx & 15;
            As[kk][r] = hcur[(size_t)(row0 + r) * DH + kb + kk];
        }
        #pragma unroll
        for (int l = 0; l < 8; l++) {
            int idx = tid + l * 256;
            int n = idx >> 4, kk = idx & 15;
            Bs[kk][n] = (n < OUTC) ? Wout[(size_t)n * DH + kb + kk] : 0.f;
        }
        __syncthreads();
        #pragma unroll
        for (int kk = 0; kk < 16; kk++) {
            float a[4], bv[8];
            #pragma unroll
            for (int i = 0; i < 4; i++) a[i] = As[kk][ty * 4 + i];
            #pragma unroll
            for (int j = 0; j < 8; j++) bv[j] = Bs[kk][tx * 8 + j];
            #pragma unroll
            for (int i = 0; i < 4; i++)
                #pragma unroll
                for (int j = 0; j < 8; j++) acc[i][j] += a[i] * bv[j];
        }
        __syncthreads();
    }

    #pragma unroll
    for (int i = 0; i < 4; i++)
        #pragma unroll
        for (int j = 0; j < 8; j++) {
            int n = tx * 8 + j;
            if (n < OUTC) ys[ty * 4 + i][n] = acc[i][j];
        }
    __syncthreads();

    // mixture transforms: 8 warps x 8 rows
    int w = tid >> 5, lane = tid & 31;
    float qacc = 0.f;
    for (int rr = 0; rr < 8; rr++) {
        int r = w * 8 + rr;
        int brow = row0 + r;
        float* orow = out + ((size_t)tstep * Bv + brow) * OUTC;
        float v = (lane < 20) ? ys[r][lane * 6] : -3.0e38f;
        float m = wmax32(v);
        float e = (lane < 20) ? __expf(v - m) : 0.f;
        float ss = wsum32(e);
        if (lane < 20) {
            orow[lane]        = e / ss;
            orow[20 + lane]   = ys[r][lane * 6 + 1];
            orow[40 + lane]   = ys[r][lane * 6 + 2];
            orow[60 + lane]   = __expf(ys[r][lane * 6 + 3]);
            orow[80 + lane]   = __expf(ys[r][lane * 6 + 4]);
            orow[100 + lane]  = tanh_f(ys[r][lane * 6 + 5]);
        } else if (lane < 23) {
            float eq = __expf(ys[r][120 + lane - 20]);
            orow[120 + lane - 20] = eq;   // normalized later by qknorm
            qacc += eq;
        }
    }
    float qs = wsum32(qacc);
    if (lane == 0) wsum[w] = qs;
    __syncthreads();
    if (tid == 0) {
        float tot = 0.f;
        #pragma unroll
        for (int i = 0; i < 8; i++) tot += wsum[i];
        d_qpart[tstep * 16 + (row0 >> 6)] = tot;
    }
    __syncthreads();
}

__device__ __forceinline__ void qknorm(float* __restrict__ out, int t) {
    float tot = 0.f;
    #pragma unroll
    for (int i = 0; i < 16; i++) tot += d_qpart[t * 16 + i];
    float inv = 1.f / tot;
    for (int idx = blockIdx.x * NTHR + threadIdx.x; idx < Bv * 3; idx += NBLK * NTHR)
        out[((size_t)t * Bv + (idx / 3)) * OUTC + 120 + (idx % 3)] *= inv;
}

// ---------------- kernels ----------------
__global__ void reset_k() { g_count = 0; g_gen = 0; }

__global__ void prep_k(const float* __restrict__ eWihF, const float* __restrict__ eWhhF,
                       const float* __restrict__ ebF,  const float* __restrict__ eWihB,
                       const float* __restrict__ ebB,  const float* __restrict__ dWih,
                       const float* __restrict__ dWhh, const float* __restrict__ s)
{
    int gt = blockIdx.x * blockDim.x + threadIdx.x;
    int gs = gridDim.x * blockDim.x;
    for (int i = gt; i < 4 * DH * DH; i += gs) {
        int n = i / DH, k = i - n * DH, j = n >> 2, g4 = n & 3;
        d_WhhD[i] = dWhh[(size_t)(g4 * DH + j) * DH + k];
    }
    for (int i = gt; i < 4 * DH * PTc; i += gs) {
        int n = i / PTc, k = i - n * PTc, j = n >> 2, g4 = n & 3;
        d_WihS[i] = dWih[(size_t)(g4 * DH + j) * (PTc + ZL) + k];
    }
    for (int i = gt; i < 4 * EH * EH; i += gs) {
        int n = i / EH, k = i - n * EH, j = n >> 2, g4 = n & 3;
        d_WhhF[i] = eWhhF[(size_t)(g4 * EH + j) * EH + k];
    }
    for (int i = gt; i < 4 * EH * PTc; i += gs) {
        int n = i / PTc, k = i - n * PTc, j = n >> 2, g4 = n & 3;
        d_WihF[i] = eWihF[(g4 * EH + j) * PTc + k];
    }
    for (int i = gt; i < 4 * EH; i += gs) {
        int j = i >> 2, g4 = i & 3;
        d_bF[i] = ebF[g4 * EH + j];
    }
    for (int i = gt; i < Bv * EH; i += gs) { d_hE[0][i] = 0.f; d_cE[i] = 0.f; }
    // backward-direction LSTM: only one step (zero state, input x[:, T-1])
    for (int i = gt; i < Bv * EH; i += gs) {
        int b = i / EH, j = i - (i / EH) * EH;
        const float* xp = s + ((size_t)b * Tv + (Tv - 1)) * PTc;
        float gv[4];
        #pragma unroll
        for (int g = 0; g < 4; g++) {
            float a = ebB[g * EH + j];
            #pragma unroll
            for (int k = 0; k < 5; k++) a += eWihB[(size_t)(g * EH + j) * PTc + k] * xp[k];
            gv[g] = a;
        }
        float c = sigf(gv[0]) * tanh_f(gv[2]);     // f-gate * 0 dropped
        d_hback[i] = sigf(gv[3]) * tanh_f(c);
    }
}

__global__ void __launch_bounds__(NTHR, 1) enc_kernel(const float* __restrict__ s) {
    __shared__ float As[16][68];
    __shared__ float Bs[16][132];
    int bid = blockIdx.x;
    for (int t = 0; t < Tv; t++) {
        const float* hprev = d_hE[t & 1];
        float* hnext = d_hE[(t + 1) & 1];
        for (int u = bid; u < 128; u += NBLK) {   // 16 row-tiles x 8 col-tiles
            int tm = u >> 3, tn = u & 7;
            gate_tile_impl(hprev, d_WhhF, d_WihF, nullptr, d_bF, s, t,
                           d_cE, hnext, tm * 64, tn * 128, EH, EH, As, Bs);
        }
        grid_sync();
    }
    // final encoder h is in d_hE[0] (256 steps, even)
}

__global__ void vae1_k(const float* __restrict__ Wmu, const float* __restrict__ bmu,
                       const float* __restrict__ Wsig, const float* __restrict__ bsig,
                       const float* __restrict__ eps)
{
    __shared__ float hrow[2 * EH];
    int b = blockIdx.x;
    for (int k = threadIdx.x; k < 2 * EH; k += blockDim.x)
        hrow[k] = (k < EH) ? d_hE[0][(size_t)b * EH + k] : d_hback[(size_t)b * EH + (k - EH)];
    __syncthreads();
    int j = threadIdx.x;
    if (j < ZL) {
        float mu = bmu[j], ps = bsig[j];
        for (int k = 0; k < 2 * EH; k++) {
            float h = hrow[k];
            mu += h * Wmu[(size_t)j * (2 * EH) + k];
            ps += h * Wsig[(size_t)j * (2 * EH) + k];
        }
        d_z[(size_t)b * ZL + j] = mu + __expf(0.5f * ps) * eps[(size_t)b * ZL + j];
    }
}

__global__ void vae2_k(const float* __restrict__ Wh0, const float* __restrict__ bh0,
                       const float* __restrict__ dWih, const float* __restrict__ db)
{
    __shared__ float zr[ZL];
    int b = blockIdx.x;
    for (int k = threadIdx.x; k < ZL; k += blockDim.x) zr[k] = d_z[(size_t)b * ZL + k];
    __syncthreads();
    for (int o = threadIdx.x; o < DH + 4 * DH; o += blockDim.x) {
        if (o < DH) {
            float a = bh0[o];
            const float* wp = Wh0 + (size_t)o * ZL;
            for (int k = 0; k < ZL; k++) a += zr[k] * wp[k];
            d_hD[0][(size_t)b * DH + o] = tanh_f(a);
            d_cD[(size_t)b * DH + o] = 0.f;
        } else {
            int n = o - DH;
            int j = n >> 2, g4 = n & 3;
            int rw = g4 * DH + j;
            float a = db[rw];
            const float* wp = dWih + (size_t)rw * (PTc + ZL) + PTc;
            for (int k = 0; k < ZL; k++) a += zr[k] * wp[k];
            d_zproj[(size_t)b * (4 * DH) + n] = a;
        }
    }
}

__global__ void __launch_bounds__(NTHR, 1) dec_kernel(const float* __restrict__ s,
    const float* __restrict__ Wout, const float* __restrict__ bout, float* __restrict__ out)
{
    __shared__ float As[16][68];
    __shared__ float Bs[16][132];
    __shared__ float ys[64][124];
    __shared__ float wsum[8];
    int bid = blockIdx.x;
    for (int t = 0; t < Tv; t++) {
        const float* hprev = d_hD[t & 1];
        float* hnext = d_hD[(t + 1) & 1];
        if (t >= 2) qknorm(out, t - 2);
        int nun = 256 + ((t >= 1) ? 16 : 0);   // 256 gate tiles, 16 y tiles (for step t-1)
        for (int u = bid; u < nun; u += NBLK) {
            if (u < 256) {
                int tm = u >> 4, tn = u & 15;
                gate_tile_impl(hprev, d_WhhD, d_WihS, d_zproj, nullptr, s, t - 1,
                               d_cD, hnext, tm * 64, tn * 128, DH, DH, As, Bs);
            } else {
                y_tile(hprev, Wout, bout, out, t - 1, (u - 256) * 64, As, Bs, ys, wsum);
            }
        }
        grid_sync();
    }
    // tail: y(255) on h in buffer 0, then final qk normalizations
    qknorm(out, 254);
    for (int u = bid; u < 16; u += NBLK)
        y_tile(d_hD[0], Wout, bout, out, 255, u * 64, As, Bs, ys, wsum);
    grid_sync();
    qknorm(out, 255);
}

// ---------------- launch ----------------
extern "C" void kernel_launch(void* const* d_in, const int* in_sizes, int n_in,
                              void* d_out, int out_size)
{
    const float* s     = (const float*)d_in[0];
    const float* eps   = (const float*)d_in[1];
    const float* eWihF = (const float*)d_in[2];
    const float* eWhhF = (const float*)d_in[3];
    const float* ebF   = (const float*)d_in[4];
    const float* eWihB = (const float*)d_in[5];
    // d_in[6] = enc_Whh_b : provably unused (backward LSTM contributes only its first step)
    const float* ebB   = (const float*)d_in[7];
    const float* Wmu   = (const float*)d_in[8];
    const float* bmu   = (const float*)d_in[9];
    const float* Wsig  = (const float*)d_in[10];
    const float* bsig  = (const float*)d_in[11];
    const float* Wh0   = (const float*)d_in[12];
    const float* bh0   = (const float*)d_in[13];
    const float* dWih  = (const float*)d_in[14];
    const float* dWhh  = (const float*)d_in[15];
    const float* db    = (const float*)d_in[16];
    const float* Wout  = (const float*)d_in[17];
    const float* bout  = (const float*)d_in[18];
    float* out = (float*)d_out;

    reset_k<<<1, 1>>>();
    prep_k<<<2048, 256>>>(eWihF, eWhhF, ebF, eWihB, ebB, dWih, dWhh, s);
    enc_kernel<<<NBLK, NTHR>>>(s);
    vae1_k<<<Bv, 128>>>(Wmu, bmu, Wsig, bsig, eps);
    vae2_k<<<Bv, 256>>>(Wh0, bh0, dWih, db);
    dec_kernel<<<NBLK, NTHR>>>(s, Wout, bout, out);
}

// round 2
// speedup vs baseline: 1.0005x; 1.0005x over previous
#include <cuda_runtime.h>
#include <math.h>
#include <stdint.h>
#include <stddef.h>

// Problem constants
#define Bv   1024
#define Tv   256
#define EH   256
#define DH   512
#define ZL   128
#define PTc  5
#define OUTC 123
#define NBLK 148
#define NTHR 256

// ---------------- device scratch (static, no allocation) ----------------
__device__ float d_WhhF[4*EH*EH];     // encoder fwd recurrent, gate-interleaved [1024][256]
__device__ float d_WihF[4*EH*PTc];    // encoder fwd input, interleaved [1024][5]
__device__ float d_bF[4*EH];          // encoder fwd bias, interleaved
__device__ float d_WhhD[4*DH*DH];     // decoder recurrent, interleaved [2048][512]
__device__ float d_WihS[4*DH*PTc];    // decoder stroke-input, interleaved [2048][5]
__device__ float d_hE[2][Bv*EH];      // encoder h double buffer
__device__ float d_cE[Bv*EH];
__device__ float d_hback[Bv*EH];      // backward-dir h (single step)
__device__ float d_z[Bv*ZL];
__device__ float d_hD[2][Bv*DH];      // decoder h double buffer
__device__ float d_cD[Bv*DH];
__device__ float d_zproj[Bv*4*DH];    // z @ Wih_z^T + b  (interleaved) [1024][2048]
__device__ float d_qpart[Tv*16];      // deterministic per-(step, row-tile) exp_qk partial sums
__device__ unsigned g_count;
__device__ volatile unsigned g_gen;

// ---------------- helpers ----------------
__device__ __forceinline__ float sigf(float x) { return 1.f / (1.f + __expf(-x)); }
__device__ __forceinline__ float tanh_f(float x) {
    float ax = fabsf(x);
    float e = __expf(2.f * ax);
    float t = 1.f - 2.f / (e + 1.f);   // e=inf -> t=1
    return copysignf(t, x);
}
__device__ __forceinline__ float wsum32(float v) {
    #pragma unroll
    for (int o = 16; o; o >>= 1) v += __shfl_xor_sync(0xffffffffu, v, o);
    return v;
}
__device__ __forceinline__ float wmax32(float v) {
    #pragma unroll
    for (int o = 16; o; o >>= 1) v = fmaxf(v, __shfl_xor_sync(0xffffffffu, v, o));
    return v;
}

// software grid barrier (all NBLK blocks co-resident: 1 block/SM, 148 <= 152 SMs)
__device__ __forceinline__ void grid_sync() {
    __threadfence();
    __syncthreads();
    if (threadIdx.x == 0) {
        unsigned gen = g_gen;
        if (atomicAdd(&g_count, 1u) == NBLK - 1) {
            g_count = 0;
            __threadfence();
            g_gen = gen + 1;
        } else {
            while (g_gen == gen) { __nanosleep(128); }
        }
    }
    __syncthreads();
    __threadfence();
}

// ---------------- fused gate GEMM + LSTM cell update ----------------
// Tile: 64 rows x 128 cols (= 32 hidden units x 4 gates). 256 threads, 4x8 per thread.
// out[b][n] = init(b,n) + x(b,:) @ Wih5[n,:]^T + hprev(b,:) @ W[n,:]^T, then cell update.
__device__ __forceinline__ void gate_tile_impl(
    const float* __restrict__ hprev,   // [Bv][K]   (K == H)
    const float* __restrict__ W,       // [4H][K]   interleaved
    const float* __restrict__ Wih5,    // [4H][5]   interleaved
    const float* __restrict__ zproj,   // [Bv][4H]  or nullptr (then bias used)
    const float* __restrict__ bias,    // [4H]      interleaved
    const float* __restrict__ s, int xt,   // xt < 0 -> s0 = (0,0,1,0,0)
    float* __restrict__ cbuf, float* __restrict__ hnext,  // [Bv][H]
    int row0, int col0, int K, int H,
    float (*As)[68], float (*Bs)[132])
{
    const int tid = threadIdx.x;
    const int tx = tid & 15, ty = tid >> 4;
    const int N4 = 4 * H;

    int ncol[8];
    #pragma unroll
    for (int j = 0; j < 8; j++) ncol[j] = col0 + ((j >> 2) << 6) + tx * 4 + (j & 3);

    float xr[4][5];
    #pragma unroll
    for (int i = 0; i < 4; i++) {
        int row = row0 + ty * 4 + i;
        if (xt < 0) {
            xr[i][0] = 0.f; xr[i][1] = 0.f; xr[i][2] = 1.f; xr[i][3] = 0.f; xr[i][4] = 0.f;
        } else {
            const float* xp = s + ((size_t)row * Tv + xt) * PTc;
            #pragma unroll
            for (int k = 0; k < 5; k++) xr[i][k] = xp[k];
        }
    }

    float acc[4][8];
    if (zproj) {
        #pragma unroll
        for (int i = 0; i < 4; i++) {
            const float* zp = zproj + (size_t)(row0 + ty * 4 + i) * N4;
            #pragma unroll
            for (int j = 0; j < 8; j++) acc[i][j] = zp[ncol[j]];
        }
    } else {
        #pragma unroll
        for (int j = 0; j < 8; j++) {
            float bi = bias[ncol[j]];
            #pragma unroll
            for (int i = 0; i < 4; i++) acc[i][j] = bi;
        }
    }
    #pragma unroll
    for (int j = 0; j < 8; j++) {
        #pragma unroll
        for (int k = 0; k < 5; k++) {
            float w = Wih5[ncol[j] * 5 + k];
            #pragma unroll
            for (int i = 0; i < 4; i++) acc[i][j] += xr[i][k] * w;
        }
    }

    for (int kb = 0; kb < K; kb += 16) {
        #pragma unroll
        for (int l = 0; l < 4; l++) {
            int idx = tid + l * 256;
            int r = idx >> 4, kk = idx & 15;
            As[kk][r] = hprev[(size_t)(row0 + r) * K + kb + kk];
        }
        #pragma unroll
        for (int l = 0; l < 8; l++) {
            int idx = tid + l * 256;
            int n = idx >> 4, kk = idx & 15;
            Bs[kk][n] = W[(size_t)(col0 + n) * K + kb + kk];
        }
        __syncthreads();
        #pragma unroll
        for (int kk = 0; kk < 16; kk++) {
            float a[4], bv[8];
            #pragma unroll
            for (int i = 0; i < 4; i++) a[i] = As[kk][ty * 4 + i];
            #pragma unroll
            for (int j = 0; j < 8; j++) bv[j] = Bs[kk][((j >> 2) << 6) + tx * 4 + (j & 3)];
            #pragma unroll
            for (int i = 0; i < 4; i++)
                #pragma unroll
                for (int j = 0; j < 8; j++) acc[i][j] += a[i] * bv[j];
        }
        __syncthreads();
    }

    // fused LSTM cell update: each thread owns 2 complete units x 4 rows
    #pragma unroll
    for (int i = 0; i < 4; i++) {
        int row = row0 + ty * 4 + i;
        #pragma unroll
        for (int jj = 0; jj < 2; jj++) {
            int u = (col0 + jj * 64 + tx * 4) >> 2;
            float gi = acc[i][jj * 4 + 0];
            float gf = acc[i][jj * 4 + 1];
            float gg = acc[i][jj * 4 + 2];
            float go = acc[i][jj * 4 + 3];
            size_t p = (size_t)row * H + u;
            float c = sigf(gf) * cbuf[p] + sigf(gi) * tanh_f(gg);
            cbuf[p] = c;
            hnext[p] = sigf(go) * tanh_f(c);
        }
    }
}

// ---------------- y projection + mixture transforms for one 64-row tile ----------------
__device__ __forceinline__ void y_tile(
    const float* __restrict__ hcur, const float* __restrict__ Wout,
    const float* __restrict__ bout, float* __restrict__ out,
    int tstep, int row0,
    float (*As)[68], float (*Bs)[132], float (*ys)[124], float* wsum)
{
    const int tid = threadIdx.x;
    const int tx = tid & 15, ty = tid >> 4;

    float acc[4][8];
    #pragma unroll
    for (int j = 0; j < 8; j++) {
        int n = tx * 8 + j;
        float bi = (n < OUTC) ? bout[n] : 0.f;
        #pragma unroll
        for (int i = 0; i < 4; i++) acc[i][j] = bi;
    }

    for (int kb = 0; kb < DH; kb += 16) {
        #pragma unroll
        for (int l = 0; l < 4; l++) {
            int idx = tid + l * 256;
            int r = idx >> 4, kk = idx & 15;
            As[kk][r] = hcur[(size_t)(row0 + r) * DH + kb + kk];
        }
        #pragma unroll
        for (int l = 0; l < 8; l++) {
            int idx = tid + l * 256;
            int n = idx >> 4, kk = idx & 15;
            Bs[kk][n] = (n < OUTC) ? Wout[(size_t)n * DH + kb + kk] : 0.f;
        }
        __syncthreads();
        #pragma unroll
        for (int kk = 0; kk < 16; kk++) {
            float a[4], bv[8];
            #pragma unroll
            for (int i = 0; i < 4; i++) a[i] = As[kk][ty * 4 + i];
            #pragma unroll
            for (int j = 0; j < 8; j++) bv[j] = Bs[kk][tx * 8 + j];
            #pragma unroll
            for (int i = 0; i < 4; i++)
                #pragma unroll
                for (int j = 0; j < 8; j++) acc[i][j] += a[i] * bv[j];
        }
        __syncthreads();
    }

    #pragma unroll
    for (int i = 0; i < 4; i++)
        #pragma unroll
        for (int j = 0; j < 8; j++) {
            int n = tx * 8 + j;
            if (n < OUTC) ys[ty * 4 + i][n] = acc[i][j];
        }
    __syncthreads();

    // mixture transforms: 8 warps x 8 rows
    int w = tid >> 5, lane = tid & 31;
    float qacc = 0.f;
    for (int rr = 0; rr < 8; rr++) {
        int r = w * 8 + rr;
        int brow = row0 + r;
        float* orow = out + ((size_t)tstep * Bv + brow) * OUTC;
        float v = (lane < 20) ? ys[r][lane * 6] : -3.0e38f;
        float m = wmax32(v);
        float e = (lane < 20) ? __expf(v - m) : 0.f;
        float ss = wsum32(e);
        if (lane < 20) {
            orow[lane]        = e / ss;
            orow[20 + lane]   = ys[r][lane * 6 + 1];
            orow[40 + lane]   = ys[r][lane * 6 + 2];
            orow[60 + lane]   = __expf(ys[r][lane * 6 + 3]);
            orow[80 + lane]   = __expf(ys[r][lane * 6 + 4]);
            orow[100 + lane]  = tanh_f(ys[r][lane * 6 + 5]);
        } else if (lane < 23) {
            float eq = __expf(ys[r][120 + lane - 20]);
            orow[120 + lane - 20] = eq;   // normalized later by qknorm
            qacc += eq;
        }
    }
    float qs = wsum32(qacc);
    if (lane == 0) wsum[w] = qs;
    __syncthreads();
    if (tid == 0) {
        float tot = 0.f;
        #pragma unroll
        for (int i = 0; i < 8; i++) tot += wsum[i];
        d_qpart[tstep * 16 + (row0 >> 6)] = tot;
    }
    __syncthreads();
}

__device__ __forceinline__ void qknorm(float* __restrict__ out, int t) {
    float tot = 0.f;
    #pragma unroll
    for (int i = 0; i < 16; i++) tot += d_qpart[t * 16 + i];
    float inv = 1.f / tot;
    for (int idx = blockIdx.x * NTHR + threadIdx.x; idx < Bv * 3; idx += NBLK * NTHR)
        out[((size_t)t * Bv + (idx / 3)) * OUTC + 120 + (idx % 3)] *= inv;
}

// ---------------- kernels ----------------
__global__ void reset_k() { g_count = 0; g_gen = 0; }

__global__ void prep_k(const float* __restrict__ eWihF, const float* __restrict__ eWhhF,
                       const float* __restrict__ ebF,  const float* __restrict__ eWihB,
                       const float* __restrict__ ebB,  const float* __restrict__ dWih,
                       const float* __restrict__ dWhh, const float* __restrict__ s)
{
    int gt = blockIdx.x * blockDim.x + threadIdx.x;
    int gs = gridDim.x * blockDim.x;
    for (int i = gt; i < 4 * DH * DH; i += gs) {
        int n = i / DH, k = i - n * DH, j = n >> 2, g4 = n & 3;
        d_WhhD[i] = dWhh[(size_t)(g4 * DH + j) * DH + k];
    }
    for (int i = gt; i < 4 * DH * PTc; i += gs) {
        int n = i / PTc, k = i - n * PTc, j = n >> 2, g4 = n & 3;
        d_WihS[i] = dWih[(size_t)(g4 * DH + j) * (PTc + ZL) + k];
    }
    for (int i = gt; i < 4 * EH * EH; i += gs) {
        int n = i / EH, k = i - n * EH, j = n >> 2, g4 = n & 3;
        d_WhhF[i] = eWhhF[(size_t)(g4 * EH + j) * EH + k];
    }
    for (int i = gt; i < 4 * EH * PTc; i += gs) {
        int n = i / PTc, k = i - n * PTc, j = n >> 2, g4 = n & 3;
        d_WihF[i] = eWihF[(g4 * EH + j) * PTc + k];
    }
    for (int i = gt; i < 4 * EH; i += gs) {
        int j = i >> 2, g4 = i & 3;
        d_bF[i] = ebF[g4 * EH + j];
    }
    for (int i = gt; i < Bv * EH; i += gs) { d_hE[0][i] = 0.f; d_cE[i] = 0.f; }
    // backward-direction LSTM: only one step (zero state, input x[:, T-1])
    for (int i = gt; i < Bv * EH; i += gs) {
        int b = i / EH, j = i - (i / EH) * EH;
        const float* xp = s + ((size_t)b * Tv + (Tv - 1)) * PTc;
        float gv[4];
        #pragma unroll
        for (int g = 0; g < 4; g++) {
            float a = ebB[g * EH + j];
            #pragma unroll
            for (int k = 0; k < 5; k++) a += eWihB[(size_t)(g * EH + j) * PTc + k] * xp[k];
            gv[g] = a;
        }
        float c = sigf(gv[0]) * tanh_f(gv[2]);     // f-gate * 0 dropped
        d_hback[i] = sigf(gv[3]) * tanh_f(c);
    }
}

__global__ void __launch_bounds__(NTHR, 1) enc_kernel(const float* __restrict__ s) {
    __shared__ float As[16][68];
    __shared__ float Bs[16][132];
    int bid = blockIdx.x;
    for (int t = 0; t < Tv; t++) {
        const float* hprev = d_hE[t & 1];
        float* hnext = d_hE[(t + 1) & 1];
        for (int u = bid; u < 128; u += NBLK) {   // 16 row-tiles x 8 col-tiles
            int tm = u >> 3, tn = u & 7;
            gate_tile_impl(hprev, d_WhhF, d_WihF, nullptr, d_bF, s, t,
                           d_cE, hnext, tm * 64, tn * 128, EH, EH, As, Bs);
        }
        grid_sync();
    }
    // final encoder h is in d_hE[0] (256 steps, even)
}

__global__ void vae1_k(const float* __restrict__ Wmu, const float* __restrict__ bmu,
                       const float* __restrict__ Wsig, const float* __restrict__ bsig,
                       const float* __restrict__ eps)
{
    __shared__ float hrow[2 * EH];
    int b = blockIdx.x;
    for (int k = threadIdx.x; k < 2 * EH; k += blockDim.x)
        hrow[k] = (k < EH) ? d_hE[0][(size_t)b * EH + k] : d_hback[(size_t)b * EH + (k - EH)];
    __syncthreads();
    int j = threadIdx.x;
    if (j < ZL) {
        float mu = bmu[j], ps = bsig[j];
        for (int k = 0; k < 2 * EH; k++) {
            float h = hrow[k];
            mu += h * Wmu[(size_t)j * (2 * EH) + k];
            ps += h * Wsig[(size_t)j * (2 * EH) + k];
        }
        d_z[(size_t)b * ZL + j] = mu + __expf(0.5f * ps) * eps[(size_t)b * ZL + j];
    }
}

__global__ void vae2_k(const float* __restrict__ Wh0, const float* __restrict__ bh0,
                       const float* __restrict__ dWih, const float* __restrict__ db)
{
    __shared__ float zr[ZL];
    int b = blockIdx.x;
    for (int k = threadIdx.x; k < ZL; k += blockDim.x) zr[k] = d_z[(size_t)b * ZL + k];
    __syncthreads();
    for (int o = threadIdx.x; o < DH + 4 * DH; o += blockDim.x) {
        if (o < DH) {
            float a = bh0[o];
            const float* wp = Wh0 + (size_t)o * ZL;
            for (int k = 0; k < ZL; k++) a += zr[k] * wp[k];
            d_hD[0][(size_t)b * DH + o] = tanh_f(a);
            d_cD[(size_t)b * DH + o] = 0.f;
        } else {
            int n = o - DH;
            int j = n >> 2, g4 = n & 3;
            int rw = g4 * DH + j;
            float a = db[rw];
            const float* wp = dWih + (size_t)rw * (PTc + ZL) + PTc;
            for (int k = 0; k < ZL; k++) a += zr[k] * wp[k];
            d_zproj[(size_t)b * (4 * DH) + n] = a;
        }
    }
}

__global__ void __launch_bounds__(NTHR, 1) dec_kernel(const float* __restrict__ s,
    const float* __restrict__ Wout, const float* __restrict__ bout, float* __restrict__ out)
{
    __shared__ float As[16][68];
    __shared__ float Bs[16][132];
    __shared__ float ys[64][124];
    __shared__ float wsum[8];
    int bid = blockIdx.x;
    for (int t = 0; t < Tv; t++) {
        const float* hprev = d_hD[t & 1];
        float* hnext = d_hD[(t + 1) & 1];
        if (t >= 2) qknorm(out, t - 2);
        int nun = 256 + ((t >= 1) ? 16 : 0);   // 256 gate tiles, 16 y tiles (for step t-1)
        for (int u = bid; u < nun; u += NBLK) {
            if (u < 256) {
                int tm = u >> 4, tn = u & 15;
                gate_tile_impl(hprev, d_WhhD, d_WihS, d_zproj, nullptr, s, t - 1,
                               d_cD, hnext, tm * 64, tn * 128, DH, DH, As, Bs);
            } else {
                y_tile(hprev, Wout, bout, out, t - 1, (u - 256) * 64, As, Bs, ys, wsum);
            }
        }
        grid_sync();
    }
    // tail: y(255) on h in buffer 0, then final qk normalizations
    qknorm(out, 254);
    for (int u = bid; u < 16; u += NBLK)
        y_tile(d_hD[0], Wout, bout, out, 255, u * 64, As, Bs, ys, wsum);
    grid_sync();
    qknorm(out, 255);
}

// ---------------- launch ----------------
extern "C" void kernel_launch(void* const* d_in, const int* in_sizes, int n_in,
                              void* d_out, int out_size)
{
    const float* s     = (const float*)d_in[0];
    const float* eps   = (const float*)d_in[1];
    const float* eWihF = (const float*)d_in[2];
    const float* eWhhF = (const float*)d_in[3];
    const float* ebF   = (const float*)d_in[4];
    const float* eWihB = (const float*)d_in[5];
    // d_in[6] = enc_Whh_b : provably unused (backward LSTM contributes only its first step)
    const float* ebB   = (const float*)d_in[7];
    const float* Wmu   = (const float*)d_in[8];
    const float* bmu   = (const float*)d_in[9];
    const float* Wsig  = (const float*)d_in[10];
    const float* bsig  = (const float*)d_in[11];
    const float* Wh0   = (const float*)d_in[12];
    const float* bh0   = (const float*)d_in[13];
    const float* dWih  = (const float*)d_in[14];
    const float* dWhh  = (const float*)d_in[15];
    const float* db    = (const float*)d_in[16];
    const float* Wout  = (const float*)d_in[17];
    const float* bout  = (const float*)d_in[18];
    float* out = (float*)d_out;

    reset_k<<<1, 1>>>();
    prep_k<<<2048, 256>>>(eWihF, eWhhF, ebF, eWihB, ebB, dWih, dWhh, s);
    enc_kernel<<<NBLK, NTHR>>>(s);
    vae1_k<<<Bv, 128>>>(Wmu, bmu, Wsig, bsig, eps);
    vae2_k<<<Bv, 256>>>(Wh0, bh0, dWih, db);
    dec_kernel<<<NBLK, NTHR>>>(s, Wout, bout, out);
}